// round 4
// baseline (speedup 1.0000x reference)
#include <cuda_runtime.h>
#include <cstdint>

#define NE    8192
#define DIM   128
#define PMAX  5
#define NNODE 512
#define TOTAL (NNODE * NNODE)

#define CTAS        128
#define THREADS     1024
#define CLUSTER     4
#define TBL_BYTES   (PMAX * NE * 4)        // 163840
#define SLICE_BYTES (TBL_BYTES / CLUSTER)  // 40960

// Precomputed dot products, layout [p][e].
__device__ float g_dots[PMAX * NE];

__device__ __forceinline__ uint32_t smem_u32(const void* p) {
    return (uint32_t)__cvta_generic_to_shared(p);
}

// ---------------------------------------------------------------------------
// Kernel 1: dots[p][e] = sum_d emb[e][d] * ev[p][d]
// 128 CTAs x 1024 threads, warp handles 2 edges: single wave.
// ---------------------------------------------------------------------------
__global__ __launch_bounds__(THREADS) void edge_dot_kernel(
        const float* __restrict__ emb, const float* __restrict__ ev) {
    const int lane = threadIdx.x & 31;
    const int w    = threadIdx.x >> 5;
    const int e0   = (blockIdx.x * 32 + w) * 2;

    float4 evr[PMAX];
#pragma unroll
    for (int p = 0; p < PMAX; ++p)
        evr[p] = __ldg(((const float4*)ev) + p * (DIM / 4) + lane);

    float4 a0 = __ldg(((const float4*)emb) + (e0    ) * (DIM / 4) + lane);
    float4 a1 = __ldg(((const float4*)emb) + (e0 + 1) * (DIM / 4) + lane);

    float pa[PMAX], pb[PMAX];
#pragma unroll
    for (int p = 0; p < PMAX; ++p) {
        pa[p] = a0.x * evr[p].x + a0.y * evr[p].y + a0.z * evr[p].z + a0.w * evr[p].w;
        pb[p] = a1.x * evr[p].x + a1.y * evr[p].y + a1.z * evr[p].z + a1.w * evr[p].w;
    }
#pragma unroll
    for (int off = 16; off > 0; off >>= 1) {
#pragma unroll
        for (int p = 0; p < PMAX; ++p) {
            pa[p] += __shfl_xor_sync(0xffffffffu, pa[p], off);
            pb[p] += __shfl_xor_sync(0xffffffffu, pb[p], off);
        }
    }
    if (lane == 0) {
#pragma unroll
        for (int p = 0; p < PMAX; ++p) {
            g_dots[p * NE + e0]     = pa[p];
            g_dots[p * NE + e0 + 1] = pb[p];
        }
    }
}

// ---------------------------------------------------------------------------
// Kernel 2: per (i,j) pair, sum dots[p][e_p] over non-padded positions, / len.
// 128 CTAs x 1024 threads x 2 pairs = 262144 exactly.
// Table filled via cluster-4 multicast bulk copy (5MB total L2 traffic instead
// of 20MB); path indices register-prefetched before the fill so the DRAM
// latency hides under it.
// ---------------------------------------------------------------------------
__global__ __launch_bounds__(THREADS, 1) __cluster_dims__(CLUSTER, 1, 1)
void gather_kernel(const int* __restrict__ paths, float* __restrict__ out) {
    extern __shared__ float s_dots[];               // 163840 bytes
    __shared__ __align__(8) unsigned long long mbar;

    const int tid    = threadIdx.x;
    const int stride = CTAS * THREADS;              // 131072
    const int idx0   = blockIdx.x * THREADS + tid;
    const int idx1   = idx0 + stride;

    // --- prefetch path indices (DRAM latency hides under the table fill) ---
    int e0[PMAX], e1[PMAX];
#pragma unroll
    for (int p = 0; p < PMAX; ++p) e0[p] = __ldg(paths + idx0 * PMAX + p);
#pragma unroll
    for (int p = 0; p < PMAX; ++p) e1[p] = __ldg(paths + idx1 * PMAX + p);

    // --- mbarrier init, cluster-visible before any multicast lands ---
    const uint32_t mb = smem_u32(&mbar);
    if (tid == 0)
        asm volatile("mbarrier.init.shared.b64 [%0], 1;" :: "r"(mb));
    __syncthreads();
    asm volatile("barrier.cluster.arrive.aligned;" ::: "memory");
    asm volatile("barrier.cluster.wait.aligned;"   ::: "memory");

    // --- each cluster CTA multicasts its 40KB slice to all 4 CTAs ---
    if (tid == 0) {
        asm volatile("mbarrier.arrive.expect_tx.shared.b64 _, [%0], %1;"
                     :: "r"(mb), "r"((uint32_t)TBL_BYTES) : "memory");
        uint32_t rank;
        asm("mov.u32 %0, %%cluster_ctarank;" : "=r"(rank));
        uint32_t    dst = smem_u32(s_dots) + rank * SLICE_BYTES;
        const char* src = (const char*)g_dots + rank * SLICE_BYTES;
        asm volatile(
            "cp.async.bulk.shared::cluster.global.mbarrier::complete_tx::bytes"
            ".multicast::cluster [%0], [%1], %2, [%3], %4;"
            :: "r"(dst), "l"(src), "r"((uint32_t)SLICE_BYTES), "r"(mb),
               "h"((unsigned short)((1u << CLUSTER) - 1u))
            : "memory");
    }

    // --- wait for all 4 slices ---
    {
        uint32_t done;
        asm volatile(
            "{\n\t.reg .pred p;\n\t"
            "mbarrier.try_wait.parity.acquire.cta.shared::cta.b64 p, [%1], 0;\n\t"
            "selp.b32 %0, 1, 0, p;\n\t}"
            : "=r"(done) : "r"(mb) : "memory");
        while (!done) {
            asm volatile(
                "{\n\t.reg .pred p;\n\t"
                "mbarrier.try_wait.parity.acquire.cta.shared::cta.b64 p, [%1], 0, 0x989680;\n\t"
                "selp.b32 %0, 1, 0, p;\n\t}"
                : "=r"(done) : "r"(mb) : "memory");
        }
    }

    // --- gather + reduce ---
    const float recip[6] = {0.f, 1.f, 0.5f, 1.f/3.f, 0.25f, 0.2f};
    {
        float acc = 0.0f; int cnt = 0;
#pragma unroll
        for (int p = 0; p < PMAX; ++p) {
            int e = e0[p];
            if (e >= 0) { acc += s_dots[p * NE + e]; ++cnt; }
        }
        out[idx0] = acc * recip[cnt];
    }
    {
        float acc = 0.0f; int cnt = 0;
#pragma unroll
        for (int p = 0; p < PMAX; ++p) {
            int e = e1[p];
            if (e >= 0) { acc += s_dots[p * NE + e]; ++cnt; }
        }
        out[idx1] = acc * recip[cnt];
    }
}

// ---------------------------------------------------------------------------
// Launch
// ---------------------------------------------------------------------------
extern "C" void kernel_launch(void* const* d_in, const int* in_sizes, int n_in,
                              void* d_out, int out_size) {
    const float* emb   = nullptr;
    const int*   paths = nullptr;
    const float* ev    = nullptr;
    for (int i = 0; i < n_in; ++i) {
        if (in_sizes[i] == NE * DIM)                  emb   = (const float*)d_in[i];
        else if (in_sizes[i] == NNODE * NNODE * PMAX) paths = (const int*)d_in[i];
        else if (in_sizes[i] == PMAX * DIM)           ev    = (const float*)d_in[i];
    }
    float* out = (float*)d_out;

    edge_dot_kernel<<<CTAS, THREADS>>>(emb, ev);

    cudaFuncSetAttribute(gather_kernel,
                         cudaFuncAttributeMaxDynamicSharedMemorySize,
                         TBL_BYTES);
    gather_kernel<<<CTAS, THREADS, TBL_BYTES>>>(paths, out);
}